// round 2
// baseline (speedup 1.0000x reference)
#include <cuda_runtime.h>
#include <cstdint>

// ---------------------------------------------------------------------------
// Problem: x(8,64,256,256) fp32
//   h  = fakequant_act( prelu( conv3x3(x, fq_w(w1,sw1)) + b1, alpha1 ), sa1 )
//   out= fakequant_act( prelu( conv3x3(h, fq_w(w2,sw2)) + b2, alpha2 ), sa2 )
// fake_quant(v,s) = clip(rint(v/s), -64, 63) * s   (round half-to-even)
// ---------------------------------------------------------------------------

#define B_   8
#define C_   64
#define H_   256
#define W_   256
#define CO_  3

// Scratch (module-load allocated; no runtime alloc)
__device__ float g_h[(size_t)B_ * C_ * H_ * W_];          // 134 MB intermediate
__device__ float g_wt1[C_ * 9 * C_];                      // [c][tap][oc] quantized w1
__device__ float g_wt2[C_ * 9 * 4];                       // [c][tap][oc(pad4)] quantized w2

static __device__ __forceinline__ float fq(float v, float s) {
    float q = rintf(v / s);
    q = fminf(fmaxf(q, -64.f), 63.f);
    return q * s;
}

// ---------------------------------------------------------------------------
// Prep: fake-quant weights (per output channel) + transpose for conv kernels
// ---------------------------------------------------------------------------
__global__ void prep_weights(const float* __restrict__ w1, const float* __restrict__ sw1,
                             const float* __restrict__ w2, const float* __restrict__ sw2) {
    int i = blockIdx.x * 256 + threadIdx.x;
    if (i < C_ * C_ * 9) {
        // w1[oc][c][ky][kx] -> g_wt1[(c*9+t)*64 + oc]
        int oc = i / (C_ * 9);
        int rem = i % (C_ * 9);
        int c = rem / 9;
        int t = rem % 9;
        g_wt1[(c * 9 + t) * C_ + oc] = fq(w1[i], sw1[oc]);
    }
    if (i < C_ * 9 * 4) {
        // g_wt2[(c*9+t)*4 + o], o in 0..3 (3 real + 1 zero pad)
        int c = i / 36;
        int rem = i % 36;
        int t = rem / 4;
        int o = rem % 4;
        float v = 0.f;
        if (o < CO_) v = fq(w2[((o * C_) + c) * 9 + t], sw2[o]);
        g_wt2[i] = v;
    }
}

// ---------------------------------------------------------------------------
// Conv1: 64->64 3x3 pad 1, + bias + PReLU + act fake-quant -> g_h
// Block: 256 thr, computes 8-row x 32-col pixel tile x all 64 out channels.
// Thread: 8 oc x 8 px register tile (64 accumulators).
// ---------------------------------------------------------------------------
__global__ __launch_bounds__(256, 2)
void conv1_kernel(const float* __restrict__ x,
                  const float* __restrict__ b1,
                  const float* __restrict__ alpha1,
                  const float* __restrict__ sa1) {
    __shared__ float xs[8][10][36];   // 8 ch chunk, 10 rows (8+halo), 34 cols (pad 36)
    __shared__ float ws[8][9][64];    // 8 ch chunk, 9 taps, 64 oc

    const int b  = blockIdx.z;
    const int y0 = blockIdx.y * 8;
    const int x0 = blockIdx.x * 32;
    const int tid = threadIdx.x;

    const int ocg = tid >> 5;              // 0..7  -> oc0 = ocg*8
    const int pxg = tid & 31;              // 0..31
    const int r   = pxg >> 2;              // 0..7 tile row
    const int c8  = (pxg & 3) << 3;        // 0,8,16,24 tile col base
    const int oc0 = ocg << 3;

    float acc[8][8];
    #pragma unroll
    for (int o = 0; o < 8; ++o)
        #pragma unroll
        for (int p = 0; p < 8; ++p) acc[o][p] = 0.f;

    const float* xb = x + (size_t)b * C_ * H_ * W_;

    for (int cc = 0; cc < C_; cc += 8) {
        __syncthreads();
        // Load x tile: 8 ch x 10 x 34 (zero-padded at image borders)
        for (int i = tid; i < 8 * 10 * 34; i += 256) {
            int ch  = i / 340;
            int rem = i % 340;
            int ry  = rem / 34;
            int rx  = rem % 34;
            int gy  = y0 + ry - 1;
            int gx  = x0 + rx - 1;
            float v = 0.f;
            if ((unsigned)gy < (unsigned)H_ && (unsigned)gx < (unsigned)W_)
                v = xb[((size_t)(cc + ch) * H_ + gy) * W_ + gx];
            xs[ch][ry][rx] = v;
        }
        // Load weights chunk: 8*9*64 floats = 1152 float4
        {
            const float4* wsrc = (const float4*)(g_wt1 + (size_t)cc * 9 * C_);
            float4* wdst = (float4*)&ws[0][0][0];
            for (int i = tid; i < 8 * 9 * 16; i += 256) wdst[i] = wsrc[i];
        }
        __syncthreads();

        #pragma unroll 1
        for (int c = 0; c < 8; ++c) {
            #pragma unroll
            for (int ky = 0; ky < 3; ++ky) {
                float xr[10];
                // aligned vector loads for first 8, scalars for halo tail
                float4 xv0 = *(const float4*)&xs[c][r + ky][c8];
                float4 xv1 = *(const float4*)&xs[c][r + ky][c8 + 4];
                xr[0] = xv0.x; xr[1] = xv0.y; xr[2] = xv0.z; xr[3] = xv0.w;
                xr[4] = xv1.x; xr[5] = xv1.y; xr[6] = xv1.z; xr[7] = xv1.w;
                xr[8] = xs[c][r + ky][c8 + 8];
                xr[9] = xs[c][r + ky][c8 + 9];
                #pragma unroll
                for (int kx = 0; kx < 3; ++kx) {
                    float4 wa = *(const float4*)&ws[c][ky * 3 + kx][oc0];
                    float4 wb = *(const float4*)&ws[c][ky * 3 + kx][oc0 + 4];
                    #pragma unroll
                    for (int p = 0; p < 8; ++p) {
                        float xv = xr[kx + p];
                        acc[0][p] += wa.x * xv;
                        acc[1][p] += wa.y * xv;
                        acc[2][p] += wa.z * xv;
                        acc[3][p] += wa.w * xv;
                        acc[4][p] += wb.x * xv;
                        acc[5][p] += wb.y * xv;
                        acc[6][p] += wb.z * xv;
                        acc[7][p] += wb.w * xv;
                    }
                }
            }
        }
    }

    // Epilogue: bias + PReLU + fake-quant, store h
    const int gy = y0 + r;
    const int gx = x0 + c8;
    #pragma unroll
    for (int o = 0; o < 8; ++o) {
        const int oc = oc0 + o;
        const float bb = b1[oc];
        const float al = alpha1[oc];
        const float s  = sa1[oc];
        float v[8];
        #pragma unroll
        for (int p = 0; p < 8; ++p) {
            float y = acc[o][p] + bb;
            y = (y >= 0.f) ? y : al * y;
            float q = rintf(y / s);
            q = fminf(fmaxf(q, -64.f), 63.f);
            v[p] = q * s;
        }
        float* dst = g_h + (((size_t)b * C_ + oc) * H_ + gy) * W_ + gx;
        *(float4*)(dst)     = make_float4(v[0], v[1], v[2], v[3]);
        *(float4*)(dst + 4) = make_float4(v[4], v[5], v[6], v[7]);
    }
}

// ---------------------------------------------------------------------------
// Conv2: 64->3 3x3 pad 1, + bias + PReLU + act fake-quant -> out
// Block: 256 thr, 4-row x 256-col tile. Thread: 3 oc x 4 px.
// All weights (64*9*4 floats) resident in smem.
// ---------------------------------------------------------------------------
__global__ __launch_bounds__(256)
void conv2_kernel(const float* __restrict__ b2,
                  const float* __restrict__ alpha2,
                  const float* __restrict__ sa2,
                  float* __restrict__ out) {
    __shared__ float xs[4][6][264];   // 4 ch chunk, 6 rows (4+halo), 258 cols (pad 264)
    __shared__ float ws[C_ * 9 * 4];  // all quantized w2, [c][tap][oc4]

    const int b  = blockIdx.z;
    const int y0 = blockIdx.y * 4;
    const int tid = threadIdx.x;
    const int r  = tid >> 6;           // 0..3
    const int c4 = (tid & 63) << 2;    // 0..252 step 4

    float acc[3][4];
    #pragma unroll
    for (int o = 0; o < 3; ++o)
        #pragma unroll
        for (int p = 0; p < 4; ++p) acc[o][p] = 0.f;

    // Load full weight set once
    {
        const float4* wsrc = (const float4*)g_wt2;
        float4* wdst = (float4*)ws;
        for (int i = tid; i < C_ * 9; i += 256) wdst[i] = wsrc[i];
    }

    const float* hb = g_h + (size_t)b * C_ * H_ * W_;

    for (int cc = 0; cc < C_; cc += 4) {
        __syncthreads();
        // Load 4 channels of 6x258 (zero-padded)
        for (int i = tid; i < 4 * 6 * 258; i += 256) {
            int ch  = i / (6 * 258);
            int rem = i % (6 * 258);
            int ry  = rem / 258;
            int rx  = rem % 258;
            int gy  = y0 + ry - 1;
            int gx  = rx - 1;
            float v = 0.f;
            if ((unsigned)gy < (unsigned)H_ && (unsigned)gx < (unsigned)W_)
                v = hb[((size_t)(cc + ch) * H_ + gy) * W_ + gx];
            xs[ch][ry][rx] = v;
        }
        __syncthreads();

        #pragma unroll
        for (int c = 0; c < 4; ++c) {
            #pragma unroll
            for (int ky = 0; ky < 3; ++ky) {
                float xr[6];
                float4 xv = *(const float4*)&xs[c][r + ky][c4];
                xr[0] = xv.x; xr[1] = xv.y; xr[2] = xv.z; xr[3] = xv.w;
                xr[4] = xs[c][r + ky][c4 + 4];
                xr[5] = xs[c][r + ky][c4 + 5];
                #pragma unroll
                for (int kx = 0; kx < 3; ++kx) {
                    float4 w = *(const float4*)&ws[(((cc + c) * 9) + ky * 3 + kx) * 4];
                    #pragma unroll
                    for (int p = 0; p < 4; ++p) {
                        float xvv = xr[kx + p];
                        acc[0][p] += w.x * xvv;
                        acc[1][p] += w.y * xvv;
                        acc[2][p] += w.z * xvv;
                    }
                }
            }
        }
    }

    // Epilogue: bias + PReLU + fake-quant, store out (8,3,256,256)
    const int gy = y0 + r;
    #pragma unroll
    for (int o = 0; o < CO_; ++o) {
        const float bb = b2[o];
        const float al = alpha2[o];
        const float s  = sa2[o];
        float v[4];
        #pragma unroll
        for (int p = 0; p < 4; ++p) {
            float y = acc[o][p] + bb;
            y = (y >= 0.f) ? y : al * y;
            float q = rintf(y / s);
            q = fminf(fmaxf(q, -64.f), 63.f);
            v[p] = q * s;
        }
        float* dst = out + (((size_t)b * CO_ + o) * H_ + gy) * W_ + c4;
        *(float4*)dst = make_float4(v[0], v[1], v[2], v[3]);
    }
}

// ---------------------------------------------------------------------------
// Launch
// Inputs (metadata order): x, w1, b1, w2, b2, alpha1, alpha2, sw1, sw2, sa1, sa2
// ---------------------------------------------------------------------------
extern "C" void kernel_launch(void* const* d_in, const int* in_sizes, int n_in,
                              void* d_out, int out_size) {
    const float* x      = (const float*)d_in[0];
    const float* w1     = (const float*)d_in[1];
    const float* b1     = (const float*)d_in[2];
    const float* w2     = (const float*)d_in[3];
    const float* b2     = (const float*)d_in[4];
    const float* alpha1 = (const float*)d_in[5];
    const float* alpha2 = (const float*)d_in[6];
    const float* sw1    = (const float*)d_in[7];
    const float* sw2    = (const float*)d_in[8];
    const float* sa1    = (const float*)d_in[9];
    const float* sa2    = (const float*)d_in[10];
    float* out = (float*)d_out;

    // 1) weight fake-quant + transpose
    prep_weights<<<(C_ * C_ * 9 + 255) / 256, 256>>>(w1, sw1, w2, sw2);

    // 2) conv1 + bias + prelu + act-quant -> g_h
    {
        dim3 grid(W_ / 32, H_ / 8, B_);   // (8, 32, 8)
        conv1_kernel<<<grid, 256>>>(x, b1, alpha1, sa1);
    }

    // 3) conv2 + bias + prelu + act-quant -> out
    {
        dim3 grid(1, H_ / 4, B_);         // (1, 64, 8)
        conv2_kernel<<<grid, 256>>>(b2, alpha2, sa2, out);
    }
}

// round 4
// speedup vs baseline: 1.1065x; 1.1065x over previous
#include <cuda_runtime.h>
#include <cstdint>

// ---------------------------------------------------------------------------
// Problem: x(8,64,256,256) fp32
//   h  = fakequant_act( prelu( conv3x3(x, fq_w(w1,sw1)) + b1, alpha1 ), sa1 )
//   out= fakequant_act( prelu( conv3x3(h, fq_w(w2,sw2)) + b2, alpha2 ), sa2 )
// fake_quant(v,s) = clip(rint(v/s), -64, 63) * s   (round half-to-even)
//
// R4 (= R3 resubmit; R3 hit an infra failure, never ran):
// packed fp32x2 FMA (fma.rn.f32x2) in both conv mainloops -> 2x fp32 rate.
// Accumulators packed over adjacent output-channel pairs so the weight operand
// is a direct 8-byte shared load (register pair); only the x-broadcast needs a
// mov.b64 pack. Per-lane numerics identical to the scalar R2 version.
// ---------------------------------------------------------------------------

#define B_   8
#define C_   64
#define H_   256
#define W_   256
#define CO_  3

typedef unsigned long long u64;

// Scratch (module-load allocated; no runtime alloc)
__device__ float g_h[(size_t)B_ * C_ * H_ * W_];          // 134 MB intermediate
__device__ float g_wt1[C_ * 9 * C_];                      // [c][tap][oc] quantized w1
__device__ float g_wt2[C_ * 9 * 4];                       // [c][tap][oc(pad4)] quantized w2

static __device__ __forceinline__ float fq(float v, float s) {
    float q = rintf(v / s);
    q = fminf(fmaxf(q, -64.f), 63.f);
    return q * s;
}

static __device__ __forceinline__ u64 pk2(float lo, float hi) {
    u64 r;
    asm("mov.b64 %0, {%1, %2};" : "=l"(r) : "f"(lo), "f"(hi));
    return r;
}
static __device__ __forceinline__ u64 ffma2(u64 a, u64 b, u64 c) {
    u64 d;
    asm("fma.rn.f32x2 %0, %1, %2, %3;" : "=l"(d) : "l"(a), "l"(b), "l"(c));
    return d;
}
static __device__ __forceinline__ void unpk2(u64 v, float& lo, float& hi) {
    asm("mov.b64 {%0, %1}, %2;" : "=f"(lo), "=f"(hi) : "l"(v));
}

// ---------------------------------------------------------------------------
// Prep: fake-quant weights (per output channel) + transpose for conv kernels
// ---------------------------------------------------------------------------
__global__ void prep_weights(const float* __restrict__ w1, const float* __restrict__ sw1,
                             const float* __restrict__ w2, const float* __restrict__ sw2) {
    int i = blockIdx.x * 256 + threadIdx.x;
    if (i < C_ * C_ * 9) {
        // w1[oc][c][ky][kx] -> g_wt1[(c*9+t)*64 + oc]
        int oc = i / (C_ * 9);
        int rem = i % (C_ * 9);
        int c = rem / 9;
        int t = rem % 9;
        g_wt1[(c * 9 + t) * C_ + oc] = fq(w1[i], sw1[oc]);
    }
    if (i < C_ * 9 * 4) {
        // g_wt2[(c*9+t)*4 + o], o in 0..3 (3 real + 1 zero pad)
        int c = i / 36;
        int rem = i % 36;
        int t = rem / 4;
        int o = rem % 4;
        float v = 0.f;
        if (o < CO_) v = fq(w2[((o * C_) + c) * 9 + t], sw2[o]);
        g_wt2[i] = v;
    }
}

// ---------------------------------------------------------------------------
// Conv1: 64->64 3x3 pad 1, + bias + PReLU + act fake-quant -> g_h
// Block: 256 thr, 8-row x 32-col pixel tile x all 64 out channels.
// Thread: 8 oc x 8 px tile, accumulators packed as 4 oc-pairs x 8 px (f32x2).
// ---------------------------------------------------------------------------
__global__ __launch_bounds__(256, 2)
void conv1_kernel(const float* __restrict__ x,
                  const float* __restrict__ b1,
                  const float* __restrict__ alpha1,
                  const float* __restrict__ sa1) {
    __shared__ float xs[8][10][36];   // 8 ch chunk, 10 rows (8+halo), 34 cols (pad 36)
    __shared__ float ws[8][9][64];    // 8 ch chunk, 9 taps, 64 oc (oc contiguous!)

    const int b  = blockIdx.z;
    const int y0 = blockIdx.y * 8;
    const int x0 = blockIdx.x * 32;
    const int tid = threadIdx.x;

    const int ocg = tid >> 5;              // 0..7  -> oc0 = ocg*8
    const int pxg = tid & 31;              // 0..31
    const int r   = pxg >> 2;              // 0..7 tile row
    const int c8  = (pxg & 3) << 3;        // 0,8,16,24 tile col base
    const int oc0 = ocg << 3;

    u64 acc2[4][8];                        // [oc-pair][px]
    #pragma unroll
    for (int j = 0; j < 4; ++j)
        #pragma unroll
        for (int p = 0; p < 8; ++p) acc2[j][p] = 0ull;

    const float* xb = x + (size_t)b * C_ * H_ * W_;

    for (int cc = 0; cc < C_; cc += 8) {
        __syncthreads();
        // Load x tile: 8 ch x 10 x 34 (zero-padded at image borders)
        for (int i = tid; i < 8 * 10 * 34; i += 256) {
            int ch  = i / 340;
            int rem = i % 340;
            int ry  = rem / 34;
            int rx  = rem % 34;
            int gy  = y0 + ry - 1;
            int gx  = x0 + rx - 1;
            float v = 0.f;
            if ((unsigned)gy < (unsigned)H_ && (unsigned)gx < (unsigned)W_)
                v = xb[((size_t)(cc + ch) * H_ + gy) * W_ + gx];
            xs[ch][ry][rx] = v;
        }
        // Load weights chunk: 8*9*64 floats = 1152 float4
        {
            const float4* wsrc = (const float4*)(g_wt1 + (size_t)cc * 9 * C_);
            float4* wdst = (float4*)&ws[0][0][0];
            for (int i = tid; i < 8 * 9 * 16; i += 256) wdst[i] = wsrc[i];
        }
        __syncthreads();

        #pragma unroll 1
        for (int c = 0; c < 8; ++c) {
            #pragma unroll
            for (int ky = 0; ky < 3; ++ky) {
                // x row: 10 values, broadcast-packed into f32x2
                float4 xv0 = *(const float4*)&xs[c][r + ky][c8];
                float4 xv1 = *(const float4*)&xs[c][r + ky][c8 + 4];
                float x8 = xs[c][r + ky][c8 + 8];
                float x9 = xs[c][r + ky][c8 + 9];
                u64 xp[10];
                xp[0] = pk2(xv0.x, xv0.x); xp[1] = pk2(xv0.y, xv0.y);
                xp[2] = pk2(xv0.z, xv0.z); xp[3] = pk2(xv0.w, xv0.w);
                xp[4] = pk2(xv1.x, xv1.x); xp[5] = pk2(xv1.y, xv1.y);
                xp[6] = pk2(xv1.z, xv1.z); xp[7] = pk2(xv1.w, xv1.w);
                xp[8] = pk2(x8, x8);       xp[9] = pk2(x9, x9);
                #pragma unroll
                for (int kx = 0; kx < 3; ++kx) {
                    // weight oc-pairs: direct 8B shared loads (oc contiguous)
                    const u64* wrow = (const u64*)&ws[c][ky * 3 + kx][oc0];
                    u64 w0 = wrow[0];
                    u64 w1 = wrow[1];
                    u64 w2 = wrow[2];
                    u64 w3 = wrow[3];
                    #pragma unroll
                    for (int p = 0; p < 8; ++p) {
                        u64 xv = xp[kx + p];
                        acc2[0][p] = ffma2(xv, w0, acc2[0][p]);
                        acc2[1][p] = ffma2(xv, w1, acc2[1][p]);
                        acc2[2][p] = ffma2(xv, w2, acc2[2][p]);
                        acc2[3][p] = ffma2(xv, w3, acc2[3][p]);
                    }
                }
            }
        }
    }

    // Epilogue: unpack, bias + PReLU + fake-quant, store h
    const int gy = y0 + r;
    const int gx = x0 + c8;
    #pragma unroll
    for (int j = 0; j < 4; ++j) {
        float alo[8], ahi[8];
        #pragma unroll
        for (int p = 0; p < 8; ++p) unpk2(acc2[j][p], alo[p], ahi[p]);

        #pragma unroll
        for (int half = 0; half < 2; ++half) {
            const int oc = oc0 + 2 * j + half;
            const float* a = half ? ahi : alo;
            const float bb = b1[oc];
            const float al = alpha1[oc];
            const float s  = sa1[oc];
            float v[8];
            #pragma unroll
            for (int p = 0; p < 8; ++p) {
                float y = a[p] + bb;
                y = (y >= 0.f) ? y : al * y;
                float q = rintf(y / s);
                q = fminf(fmaxf(q, -64.f), 63.f);
                v[p] = q * s;
            }
            float* dst = g_h + (((size_t)b * C_ + oc) * H_ + gy) * W_ + gx;
            *(float4*)(dst)     = make_float4(v[0], v[1], v[2], v[3]);
            *(float4*)(dst + 4) = make_float4(v[4], v[5], v[6], v[7]);
        }
    }
}

// ---------------------------------------------------------------------------
// Conv2: 64->3 3x3 pad 1, + bias + PReLU + act fake-quant -> out
// Block: 256 thr, 4-row x 256-col tile. Thread: 4 oc (3 real + pad) x 4 px,
// packed as 2 oc-pairs (f32x2).
// ---------------------------------------------------------------------------
__global__ __launch_bounds__(256)
void conv2_kernel(const float* __restrict__ b2,
                  const float* __restrict__ alpha2,
                  const float* __restrict__ sa2,
                  float* __restrict__ out) {
    __shared__ float xs[4][6][264];   // 4 ch chunk, 6 rows (4+halo), 258 cols (pad 264)
    __shared__ float ws[C_ * 9 * 4];  // all quantized w2, [c][tap][oc4]

    const int b  = blockIdx.z;
    const int y0 = blockIdx.y * 4;
    const int tid = threadIdx.x;
    const int r  = tid >> 6;           // 0..3
    const int c4 = (tid & 63) << 2;    // 0..252 step 4

    u64 acc2[2][4];                    // [oc-pair][px]
    #pragma unroll
    for (int j = 0; j < 2; ++j)
        #pragma unroll
        for (int p = 0; p < 4; ++p) acc2[j][p] = 0ull;

    // Load full weight set once
    {
        const float4* wsrc = (const float4*)g_wt2;
        float4* wdst = (float4*)ws;
        for (int i = tid; i < C_ * 9; i += 256) wdst[i] = wsrc[i];
    }

    const float* hb = g_h + (size_t)b * C_ * H_ * W_;

    for (int cc = 0; cc < C_; cc += 4) {
        __syncthreads();
        // Load 4 channels of 6x258 (zero-padded)
        for (int i = tid; i < 4 * 6 * 258; i += 256) {
            int ch  = i / (6 * 258);
            int rem = i % (6 * 258);
            int ry  = rem / 258;
            int rx  = rem % 258;
            int gy  = y0 + ry - 1;
            int gx  = rx - 1;
            float v = 0.f;
            if ((unsigned)gy < (unsigned)H_ && (unsigned)gx < (unsigned)W_)
                v = hb[((size_t)(cc + ch) * H_ + gy) * W_ + gx];
            xs[ch][ry][rx] = v;
        }
        __syncthreads();

        #pragma unroll
        for (int c = 0; c < 4; ++c) {
            #pragma unroll
            for (int ky = 0; ky < 3; ++ky) {
                float4 xv = *(const float4*)&xs[c][r + ky][c4];
                float x4 = xs[c][r + ky][c4 + 4];
                float x5 = xs[c][r + ky][c4 + 5];
                u64 xp[6];
                xp[0] = pk2(xv.x, xv.x); xp[1] = pk2(xv.y, xv.y);
                xp[2] = pk2(xv.z, xv.z); xp[3] = pk2(xv.w, xv.w);
                xp[4] = pk2(x4, x4);     xp[5] = pk2(x5, x5);
                #pragma unroll
                for (int kx = 0; kx < 3; ++kx) {
                    const u64* wrow = (const u64*)&ws[(((cc + c) * 9) + ky * 3 + kx) * 4];
                    u64 w0 = wrow[0];
                    u64 w1 = wrow[1];
                    #pragma unroll
                    for (int p = 0; p < 4; ++p) {
                        u64 xvv = xp[kx + p];
                        acc2[0][p] = ffma2(xvv, w0, acc2[0][p]);
                        acc2[1][p] = ffma2(xvv, w1, acc2[1][p]);
                    }
                }
            }
        }
    }

    // Epilogue: unpack, bias + PReLU + fake-quant, store out (8,3,256,256)
    const int gy = y0 + r;
    float accf[4][4];
    #pragma unroll
    for (int j = 0; j < 2; ++j)
        #pragma unroll
        for (int p = 0; p < 4; ++p)
            unpk2(acc2[j][p], accf[2 * j][p], accf[2 * j + 1][p]);

    #pragma unroll
    for (int o = 0; o < CO_; ++o) {
        const float bb = b2[o];
        const float al = alpha2[o];
        const float s  = sa2[o];
        float v[4];
        #pragma unroll
        for (int p = 0; p < 4; ++p) {
            float y = accf[o][p] + bb;
            y = (y >= 0.f) ? y : al * y;
            float q = rintf(y / s);
            q = fminf(fmaxf(q, -64.f), 63.f);
            v[p] = q * s;
        }
        float* dst = out + (((size_t)b * CO_ + o) * H_ + gy) * W_ + c4;
        *(float4*)dst = make_float4(v[0], v[1], v[2], v[3]);
    }
}

// ---------------------------------------------------------------------------
// Launch
// Inputs (metadata order): x, w1, b1, w2, b2, alpha1, alpha2, sw1, sw2, sa1, sa2
// ---------------------------------------------------------------------------
extern "C" void kernel_launch(void* const* d_in, const int* in_sizes, int n_in,
                              void* d_out, int out_size) {
    const float* x      = (const float*)d_in[0];
    const float* w1     = (const float*)d_in[1];
    const float* b1     = (const float*)d_in[2];
    const float* w2     = (const float*)d_in[3];
    const float* b2     = (const float*)d_in[4];
    const float* alpha1 = (const float*)d_in[5];
    const float* alpha2 = (const float*)d_in[6];
    const float* sw1    = (const float*)d_in[7];
    const float* sw2    = (const float*)d_in[8];
    const float* sa1    = (const float*)d_in[9];
    const float* sa2    = (const float*)d_in[10];
    float* out = (float*)d_out;

    // 1) weight fake-quant + transpose
    prep_weights<<<(C_ * C_ * 9 + 255) / 256, 256>>>(w1, sw1, w2, sw2);

    // 2) conv1 + bias + prelu + act-quant -> g_h
    {
        dim3 grid(W_ / 32, H_ / 8, B_);   // (8, 32, 8)
        conv1_kernel<<<grid, 256>>>(x, b1, alpha1, sa1);
    }

    // 3) conv2 + bias + prelu + act-quant -> out
    {
        dim3 grid(1, H_ / 4, B_);         // (1, 64, 8)
        conv2_kernel<<<grid, 256>>>(b2, alpha2, sa2, out);
    }
}